// round 2
// baseline (speedup 1.0000x reference)
#include <cuda_runtime.h>

typedef unsigned long long u64;

#define HID 10

struct Params {
    const float* W[9];
    const float* b[9];
};

// Shared weight stash: weights duplicated into both halves of a float2 so a
// single LDS.64 broadcast feeds packed f32x2 FMAs.
struct SW {
    float2 W1[2][HID];        // layer 1 (2 -> 10), duplicated
    float2 Wh[7][HID][HID];   // layers 2..8 (10 -> 10), duplicated
    float2 W9[HID];           // layer 9 (10 -> 1), duplicated
    float  b1[HID];
    float  bh[7][HID];
    float  b9;
};

__device__ __forceinline__ u64 pk2(float lo, float hi) {
    u64 r; asm("mov.b64 %0,{%1,%2};" : "=l"(r) : "f"(lo), "f"(hi)); return r;
}
__device__ __forceinline__ void upk2(u64 v, float& lo, float& hi) {
    asm("mov.b64 {%0,%1},%2;" : "=f"(lo), "=f"(hi) : "l"(v));
}
__device__ __forceinline__ u64 fma2(u64 a, u64 b, u64 c) {
    u64 d; asm("fma.rn.f32x2 %0,%1,%2,%3;" : "=l"(d) : "l"(a), "l"(b), "l"(c)); return d;
}
__device__ __forceinline__ u64 mul2(u64 a, u64 b) {
    u64 d; asm("mul.rn.f32x2 %0,%1,%2;" : "=l"(d) : "l"(a), "l"(b)); return d;
}

// Accurate fast tanh: t = 1 - 2/(exp(2z)+1), clamped so exp stays finite.
__device__ __forceinline__ float tanh_fast(float z) {
    float zc = fminf(fmaxf(z, -15.0f), 15.0f);
    float e  = __expf(2.0f * zc);
    return 1.0f - __fdividef(2.0f, e + 1.0f);
}

__device__ __forceinline__ void load_weights(SW& s, const Params& p) {
    int t = threadIdx.x;
    for (int i = t; i < 2 * HID; i += blockDim.x) {
        float w = p.W[0][i];
        s.W1[i / HID][i % HID] = make_float2(w, w);
    }
    for (int l = 0; l < 7; l++)
        for (int i = t; i < HID * HID; i += blockDim.x) {
            float w = p.W[l + 1][i];
            s.Wh[l][i / HID][i % HID] = make_float2(w, w);
        }
    for (int i = t; i < HID; i += blockDim.x) {
        float w = p.W[8][i];
        s.W9[i] = make_float2(w, w);
    }
    for (int i = t; i < HID; i += blockDim.x) s.b1[i] = p.b[0][i];
    for (int l = 0; l < 7; l++)
        for (int i = t; i < HID; i += blockDim.x) s.bh[l][i] = p.b[l + 1][i];
    if (t == 0) s.b9 = p.b[8][0];
}

// ---------------------------------------------------------------------------
// Fused kernel.
//  Blocks [0, nfBlocks): jet path, 2 points/thread (512 points per 256-thread
//    block). 2nd-order forward-mode AD: P = (u, u_xx-jet), Q = (u_x, u_t).
//  Blocks [nfBlocks, ..): forward-only path for initial/boundary points.
// ---------------------------------------------------------------------------
__global__ void __launch_bounds__(256, 1)
fused_kernel(const float* __restrict__ Xf,
             const float* __restrict__ p0, const float* __restrict__ p1,
             const float* __restrict__ p2,
             Params p, float* __restrict__ out,
             int nf, int n0, int nb,
             int offF, int offUX, int offUXX, int off0)
{
    __shared__ SW s;
    load_weights(s, p);
    __syncthreads();

    const int nfBlocks = (nf + 511) >> 9;

    if ((int)blockIdx.x >= nfBlocks) {
        // ---------------- forward-only path ----------------
        int i = (blockIdx.x - nfBlocks) * blockDim.x + threadIdx.x;
        int total = n0 + 2 * nb;
        if (i >= total) return;

        const float* src;
        int loc, off;
        if (i < n0)           { src = p0; loc = i;           off = off0; }
        else if (i < n0 + nb) { src = p1; loc = i - n0;      off = off0 + n0; }
        else                  { src = p2; loc = i - n0 - nb; off = off0 + n0 + nb; }

        float x  = src[2 * loc + 0];
        float tt = src[2 * loc + 1];

        float h[HID];
        #pragma unroll
        for (int j = 0; j < HID; j++)
            h[j] = tanh_fast(fmaf(x, s.W1[0][j].x, fmaf(tt, s.W1[1][j].x, s.b1[j])));

        #pragma unroll 1
        for (int l = 0; l < 7; l++) {
            float z[HID];
            #pragma unroll
            for (int j = 0; j < HID; j++) z[j] = s.bh[l][j];
            #pragma unroll
            for (int k = 0; k < HID; k++) {
                float hk = h[k];
                #pragma unroll
                for (int j = 0; j < HID; j++)
                    z[j] = fmaf(hk, s.Wh[l][k][j].x, z[j]);
            }
            #pragma unroll
            for (int j = 0; j < HID; j++) h[j] = tanh_fast(z[j]);
        }

        float u = s.b9;
        #pragma unroll
        for (int k = 0; k < HID; k++) u = fmaf(h[k], s.W9[k].x, u);

        out[off + loc] = u;
        return;
    }

    // ---------------- jet path: 2 points per thread ----------------
    int i0 = blockIdx.x * 512 + threadIdx.x;
    int i1 = i0 + 256;
    int c0 = min(i0, nf - 1);
    int c1 = min(i1, nf - 1);

    float2 xy0 = reinterpret_cast<const float2*>(Xf)[c0];
    float2 xy1 = reinterpret_cast<const float2*>(Xf)[c1];

    u64 P0[HID], Q0[HID], P1[HID], Q1[HID];

    // Layer 1: input (x,t); a_x=(1,0), a_t=(0,1), a_xx=0.
    #pragma unroll
    for (int j = 0; j < HID; j++) {
        float w0 = s.W1[0][j].x;
        float w1 = s.W1[1][j].x;
        float b  = s.b1[j];

        float z0  = fmaf(xy0.x, w0, fmaf(xy0.y, w1, b));
        float t0  = tanh_fast(z0);
        float sv0 = fmaf(-t0, t0, 1.0f);
        P0[j] = pk2(t0, -2.0f * t0 * sv0 * w0 * w0);
        Q0[j] = pk2(sv0 * w0, sv0 * w1);

        float z1  = fmaf(xy1.x, w0, fmaf(xy1.y, w1, b));
        float t1  = tanh_fast(z1);
        float sv1 = fmaf(-t1, t1, 1.0f);
        P1[j] = pk2(t1, -2.0f * t1 * sv1 * w0 * w0);
        Q1[j] = pk2(sv1 * w0, sv1 * w1);
    }

    // Hidden layers 2..8
    #pragma unroll 1
    for (int l = 0; l < 7; l++) {
        u64 zP0[HID], zQ0[HID], zP1[HID], zQ1[HID];
        #pragma unroll
        for (int j = 0; j < HID; j++) {
            u64 bz = pk2(s.bh[l][j], 0.0f);
            zP0[j] = bz; zP1[j] = bz;
            zQ0[j] = 0ull; zQ1[j] = 0ull;
        }
        #pragma unroll
        for (int k = 0; k < HID; k++) {
            u64 a0 = P0[k], q0 = Q0[k];
            u64 a1 = P1[k], q1 = Q1[k];
            #pragma unroll
            for (int j = 0; j < HID; j++) {
                u64 w = *reinterpret_cast<const u64*>(&s.Wh[l][k][j]);
                zP0[j] = fma2(a0, w, zP0[j]);
                zQ0[j] = fma2(q0, w, zQ0[j]);
                zP1[j] = fma2(a1, w, zP1[j]);
                zQ1[j] = fma2(q1, w, zQ1[j]);
            }
        }
        #pragma unroll
        for (int j = 0; j < HID; j++) {
            float z0, zxx0, zx0, zt0;
            upk2(zP0[j], z0, zxx0); upk2(zQ0[j], zx0, zt0);
            float t0  = tanh_fast(z0);
            float sv0 = fmaf(-t0, t0, 1.0f);
            P0[j] = pk2(t0, fmaf(sv0, zxx0, -2.0f * t0 * sv0 * zx0 * zx0));
            Q0[j] = mul2(zQ0[j], pk2(sv0, sv0));

            float z1, zxx1, zx1, zt1;
            upk2(zP1[j], z1, zxx1); upk2(zQ1[j], zx1, zt1);
            float t1  = tanh_fast(z1);
            float sv1 = fmaf(-t1, t1, 1.0f);
            P1[j] = pk2(t1, fmaf(sv1, zxx1, -2.0f * t1 * sv1 * zx1 * zx1));
            Q1[j] = mul2(zQ1[j], pk2(sv1, sv1));
        }
    }

    // Output layer (10 -> 1), linear.
    u64 aP0 = pk2(s.b9, 0.0f), aQ0 = 0ull;
    u64 aP1 = aP0,             aQ1 = 0ull;
    #pragma unroll
    for (int k = 0; k < HID; k++) {
        u64 w = *reinterpret_cast<const u64*>(&s.W9[k]);
        aP0 = fma2(P0[k], w, aP0);
        aQ0 = fma2(Q0[k], w, aQ0);
        aP1 = fma2(P1[k], w, aP1);
        aQ1 = fma2(Q1[k], w, aQ1);
    }

    const float nu = 0.0031830988618379067f;   // 0.01 / pi

    float u0, uxx0, ux0, ut0;
    upk2(aP0, u0, uxx0); upk2(aQ0, ux0, ut0);
    float f0 = fmaf(u0, ux0, fmaf(-nu, uxx0, ut0));

    float u1, uxx1, ux1, ut1;
    upk2(aP1, u1, uxx1); upk2(aQ1, ux1, ut1);
    float f1 = fmaf(u1, ux1, fmaf(-nu, uxx1, ut1));

    if (i0 < nf) {
        out[i0]          = u0;
        out[offF + i0]   = f0;
        out[offUX + i0]  = ux0;
        out[offUXX + i0] = uxx0;
    }
    if (i1 < nf) {
        out[i1]          = u1;
        out[offF + i1]   = f1;
        out[offUX + i1]  = ux1;
        out[offUXX + i1] = uxx1;
    }
}

// ---------------------------------------------------------------------------
// Output layout (reference tuple order, concatenated):
//   [0, nf) u_pred_f | [nf, +n0) u_pred_0 | [+nb) left | [+nb) right
//   | [+nf) f | [+nf) u_x | [+nf) u_xx
// ---------------------------------------------------------------------------
extern "C" void kernel_launch(void* const* d_in, const int* in_sizes, int n_in,
                              void* d_out, int out_size)
{
    Params p;
    for (int i = 0; i < 9; i++) {
        p.W[i] = (const float*)d_in[4 + 2 * i];
        p.b[i] = (const float*)d_in[5 + 2 * i];
    }
    const float* Xf = (const float*)d_in[0];
    const float* x0 = (const float*)d_in[1];
    const float* xl = (const float*)d_in[2];
    const float* xr = (const float*)d_in[3];

    int nf = in_sizes[0] / 2;
    int n0 = in_sizes[1] / 2;
    int nb = in_sizes[2] / 2;

    float* out = (float*)d_out;

    int off0   = nf;
    int offF   = nf + n0 + 2 * nb;
    int offUX  = offF + nf;
    int offUXX = offUX + nf;

    int nfBlocks  = (nf + 511) / 512;
    int fwdBlocks = (n0 + 2 * nb + 255) / 256;

    fused_kernel<<<nfBlocks + fwdBlocks, 256>>>(
        Xf, x0, xl, xr, p, out, nf, n0, nb, offF, offUX, offUXX, off0);
}

// round 3
// speedup vs baseline: 1.0275x; 1.0275x over previous
#include <cuda_runtime.h>

typedef unsigned long long u64;

#define HID 10

struct Params {
    const float* W[9];
    const float* b[9];
};

// Shared weight stash: weights duplicated into both halves of a float2 so a
// single LDS.64 broadcast feeds packed f32x2 FMAs.
struct SW {
    float2 W1[2][HID];        // layer 1 (2 -> 10), duplicated
    float2 Wh[7][HID][HID];   // layers 2..8 (10 -> 10), duplicated
    float2 W9[HID];           // layer 9 (10 -> 1), duplicated
    float  b1[HID];
    float  bh[7][HID];
    float  b9;
};

__device__ __forceinline__ u64 pk2(float lo, float hi) {
    u64 r; asm("mov.b64 %0,{%1,%2};" : "=l"(r) : "f"(lo), "f"(hi)); return r;
}
__device__ __forceinline__ void upk2(u64 v, float& lo, float& hi) {
    asm("mov.b64 {%0,%1},%2;" : "=f"(lo), "=f"(hi) : "l"(v));
}
__device__ __forceinline__ u64 fma2(u64 a, u64 b, u64 c) {
    u64 d; asm("fma.rn.f32x2 %0,%1,%2,%3;" : "=l"(d) : "l"(a), "l"(b), "l"(c)); return d;
}
__device__ __forceinline__ u64 mul2(u64 a, u64 b) {
    u64 d; asm("mul.rn.f32x2 %0,%1,%2;" : "=l"(d) : "l"(a), "l"(b)); return d;
}

// Clamp-free fast tanh: t = 1 - 2/(1 + 2^(2*log2(e)*z)).
// ex2 saturates to +inf / 0 at the extremes, rcp maps those to 0 / 1,
// giving exactly +-1 — no clamp needed, NaN-free for all finite z.
__device__ __forceinline__ float tanh_fast(float z) {
    float p = z * 2.8853900817779268f;   // 2 * log2(e)
    float e;
    asm("ex2.approx.f32 %0, %1;" : "=f"(e) : "f"(p));
    float r;
    asm("rcp.approx.f32 %0, %1;" : "=f"(r) : "f"(e + 1.0f));
    return fmaf(-2.0f, r, 1.0f);
}

__device__ __forceinline__ void load_weights(SW& s, const Params& p) {
    int t = threadIdx.x;
    for (int i = t; i < 2 * HID; i += blockDim.x) {
        float w = p.W[0][i];
        s.W1[i / HID][i % HID] = make_float2(w, w);
    }
    for (int l = 0; l < 7; l++)
        for (int i = t; i < HID * HID; i += blockDim.x) {
            float w = p.W[l + 1][i];
            s.Wh[l][i / HID][i % HID] = make_float2(w, w);
        }
    for (int i = t; i < HID; i += blockDim.x) {
        float w = p.W[8][i];
        s.W9[i] = make_float2(w, w);
    }
    for (int i = t; i < HID; i += blockDim.x) s.b1[i] = p.b[0][i];
    for (int l = 0; l < 7; l++)
        for (int i = t; i < HID; i += blockDim.x) s.bh[l][i] = p.b[l + 1][i];
    if (t == 0) s.b9 = p.b[8][0];
}

// ---------------------------------------------------------------------------
// Fused kernel, 128 threads/block, 5 blocks/SM (20 warps).
//  Blocks [0, nfBlocks): jet path, 1 point/thread.
//    2nd-order forward-mode AD: P = (u, u_xx-jet), Q = (u_x, u_t).
//  Blocks [nfBlocks, ..): forward-only path for initial/boundary points.
// ---------------------------------------------------------------------------
__global__ void __launch_bounds__(128, 5)
fused_kernel(const float* __restrict__ Xf,
             const float* __restrict__ p0, const float* __restrict__ p1,
             const float* __restrict__ p2,
             Params p, float* __restrict__ out,
             int nf, int n0, int nb)
{
    __shared__ SW s;
    load_weights(s, p);
    __syncthreads();

    const int nfBlocks = (nf + 127) >> 7;

    if ((int)blockIdx.x >= nfBlocks) {
        // ---------------- forward-only path ----------------
        int i = (blockIdx.x - nfBlocks) * blockDim.x + threadIdx.x;
        int total = n0 + 2 * nb;
        if (i >= total) return;

        const float* src;
        int loc, off;
        if (i < n0)           { src = p0; loc = i;           off = nf; }
        else if (i < n0 + nb) { src = p1; loc = i - n0;      off = nf + n0; }
        else                  { src = p2; loc = i - n0 - nb; off = nf + n0 + nb; }

        float x  = src[2 * loc + 0];
        float tt = src[2 * loc + 1];

        float h[HID];
        #pragma unroll
        for (int j = 0; j < HID; j++)
            h[j] = tanh_fast(fmaf(x, s.W1[0][j].x, fmaf(tt, s.W1[1][j].x, s.b1[j])));

        #pragma unroll 1
        for (int l = 0; l < 7; l++) {
            float z[HID];
            #pragma unroll
            for (int j = 0; j < HID; j++) z[j] = s.bh[l][j];
            #pragma unroll
            for (int k = 0; k < HID; k++) {
                float hk = h[k];
                #pragma unroll
                for (int j = 0; j < HID; j++)
                    z[j] = fmaf(hk, s.Wh[l][k][j].x, z[j]);
            }
            #pragma unroll
            for (int j = 0; j < HID; j++) h[j] = tanh_fast(z[j]);
        }

        float u = s.b9;
        #pragma unroll
        for (int k = 0; k < HID; k++) u = fmaf(h[k], s.W9[k].x, u);

        out[off + loc] = u;
        return;
    }

    // ---------------- jet path: 1 point per thread ----------------
    int i = blockIdx.x * blockDim.x + threadIdx.x;
    int c = min(i, nf - 1);

    float2 xy = reinterpret_cast<const float2*>(Xf)[c];

    u64 P[HID], Q[HID];

    // Layer 1: input (x,t); a_x=(1,0), a_t=(0,1), a_xx=0.
    #pragma unroll
    for (int j = 0; j < HID; j++) {
        float w0 = s.W1[0][j].x;
        float w1 = s.W1[1][j].x;
        float z  = fmaf(xy.x, w0, fmaf(xy.y, w1, s.b1[j]));
        float t  = tanh_fast(z);
        float sv = fmaf(-t, t, 1.0f);
        P[j] = pk2(t, -2.0f * t * sv * w0 * w0);   // zxx = 0, zx = w0
        Q[j] = pk2(sv * w0, sv * w1);
    }

    // Hidden layers 2..8
    #pragma unroll 1
    for (int l = 0; l < 7; l++) {
        u64 zP[HID], zQ[HID];
        #pragma unroll
        for (int j = 0; j < HID; j++) {
            zP[j] = pk2(s.bh[l][j], 0.0f);
            zQ[j] = 0ull;
        }
        #pragma unroll
        for (int k = 0; k < HID; k++) {
            u64 Pk = P[k], Qk = Q[k];
            #pragma unroll
            for (int j = 0; j < HID; j++) {
                u64 w = *reinterpret_cast<const u64*>(&s.Wh[l][k][j]);
                zP[j] = fma2(Pk, w, zP[j]);
                zQ[j] = fma2(Qk, w, zQ[j]);
            }
        }
        #pragma unroll
        for (int j = 0; j < HID; j++) {
            float z, zxx;  upk2(zP[j], z, zxx);
            float zx, zt;  upk2(zQ[j], zx, zt);
            (void)zt;
            float t  = tanh_fast(z);
            float sv = fmaf(-t, t, 1.0f);
            P[j] = pk2(t, fmaf(sv, zxx, -2.0f * t * sv * zx * zx));
            Q[j] = mul2(zQ[j], pk2(sv, sv));
        }
    }

    // Output layer (10 -> 1), linear.
    u64 aP = pk2(s.b9, 0.0f);
    u64 aQ = 0ull;
    #pragma unroll
    for (int k = 0; k < HID; k++) {
        u64 w = *reinterpret_cast<const u64*>(&s.W9[k]);
        aP = fma2(P[k], w, aP);
        aQ = fma2(Q[k], w, aQ);
    }
    float u, uxx;  upk2(aP, u, uxx);
    float ux, ut;  upk2(aQ, ux, ut);

    const float nu = 0.0031830988618379067f;   // 0.01 / pi
    float f = fmaf(u, ux, fmaf(-nu, uxx, ut)); // u_t + u*u_x - nu*u_xx

    if (i < nf) {
        int offF = nf + n0 + 2 * nb;   // recomputed here to keep them cold
        out[i]               = u;
        out[offF + i]        = f;
        out[offF + nf + i]   = ux;
        out[offF + 2*nf + i] = uxx;
    }
}

// ---------------------------------------------------------------------------
// Output layout (reference tuple order, concatenated):
//   [0, nf) u_pred_f | [nf, +n0) u_pred_0 | [+nb) left | [+nb) right
//   | [+nf) f | [+nf) u_x | [+nf) u_xx
// ---------------------------------------------------------------------------
extern "C" void kernel_launch(void* const* d_in, const int* in_sizes, int n_in,
                              void* d_out, int out_size)
{
    Params p;
    for (int i = 0; i < 9; i++) {
        p.W[i] = (const float*)d_in[4 + 2 * i];
        p.b[i] = (const float*)d_in[5 + 2 * i];
    }
    const float* Xf = (const float*)d_in[0];
    const float* x0 = (const float*)d_in[1];
    const float* xl = (const float*)d_in[2];
    const float* xr = (const float*)d_in[3];

    int nf = in_sizes[0] / 2;
    int n0 = in_sizes[1] / 2;
    int nb = in_sizes[2] / 2;

    float* out = (float*)d_out;

    int nfBlocks  = (nf + 127) / 128;
    int fwdBlocks = (n0 + 2 * nb + 127) / 128;

    fused_kernel<<<nfBlocks + fwdBlocks, 128>>>(
        Xf, x0, xl, xr, p, out, nf, n0, nb);
}